// round 11
// baseline (speedup 1.0000x reference)
#include <cuda_runtime.h>
#include <math.h>

// ---------------------------------------------------------------------------
// Problem constants
// ---------------------------------------------------------------------------
#define NNODE   2048
#define DMODEL  256
#define NHEAD   8
#define DHEAD   32
#define NEDGE   65536
#define DFF     1024
#define DFEAT   128
#define DOUTF   128
#define MAXDEG  512
#define NN_TOT  (2048u*2048u)   // N*N
#define ECAP    6144            // max edges per 64-row block (mean 2048, sd ~45)

// ---------------------------------------------------------------------------
// Scratch (device globals; no dynamic allocation allowed)
// ---------------------------------------------------------------------------
__device__ float g_h   [NNODE*DMODEL];
__device__ float g_xn  [NNODE*DMODEL];
__device__ float g_q   [NNODE*DMODEL];
__device__ float g_k   [NNODE*DMODEL];
__device__ float g_v   [NNODE*DMODEL];
__device__ float g_attn[NNODE*DMODEL];
__device__ float g_ffn [NNODE*DFF];
__device__ int   g_din [NNODE];
__device__ int   g_dout[NNODE];
__device__ int   g_rowptr[NNODE + 1];
__device__ int   g_cur [NNODE];
__device__ unsigned g_ecsr[NEDGE];   // packed (src<<14)|(type<<11)|dst

// ---------------------------------------------------------------------------
// Helpers
// ---------------------------------------------------------------------------
__device__ __forceinline__ float gelu_f(float x) {
    return 0.5f * x * (1.0f + erff(x * 0.70710678118654752440f));
}

// ---------------------------------------------------------------------------
// Degrees
// ---------------------------------------------------------------------------
__global__ void deg_zero_kernel() {
    int i = blockIdx.x * blockDim.x + threadIdx.x;
    if (i < NNODE) { g_din[i] = 0; g_dout[i] = 0; }
}
__global__ void deg_acc_kernel(const int* __restrict__ ei) {
    int e = blockIdx.x * blockDim.x + threadIdx.x;
    if (e >= NEDGE) return;
    atomicAdd(&g_dout[ei[e]], 1);          // src -> out-degree
    atomicAdd(&g_din [ei[NEDGE + e]], 1);  // dst -> in-degree
}

// ---------------------------------------------------------------------------
// CSR build: exclusive scan of out-degree (1 block, 256 thr x 8 vals)
// ---------------------------------------------------------------------------
__global__ __launch_bounds__(256)
void csr_scan_kernel() {
    __shared__ int ws[8];
    int t = threadIdx.x;
    int base = t * 8;
    int v[8];
    int tsum = 0;
    #pragma unroll
    for (int i = 0; i < 8; i++) { v[i] = g_dout[base + i]; tsum += v[i]; }
    int lane = t & 31, w = t >> 5;
    int inc = tsum;
    #pragma unroll
    for (int o = 1; o < 32; o <<= 1) {
        int n = __shfl_up_sync(0xffffffffu, inc, o);
        if (lane >= o) inc += n;
    }
    if (lane == 31) ws[w] = inc;
    __syncthreads();
    if (t == 0) {
        int run = 0;
        #pragma unroll
        for (int i = 0; i < 8; i++) { int tmp = ws[i]; ws[i] = run; run += tmp; }
    }
    __syncthreads();
    int run = inc - tsum + ws[w];   // exclusive prefix for this thread
    #pragma unroll
    for (int i = 0; i < 8; i++) {
        g_rowptr[base + i] = run;
        g_cur[base + i] = 0;
        run += v[i];
    }
    if (t == 255) g_rowptr[NNODE] = run;
}

__global__ void csr_scatter_kernel(const int* __restrict__ ei,
                                   const int* __restrict__ et) {
    int e = blockIdx.x * blockDim.x + threadIdx.x;
    if (e >= NEDGE) return;
    unsigned src = (unsigned)ei[e];
    unsigned dst = (unsigned)ei[NEDGE + e];
    unsigned ty  = (unsigned)et[e];
    int idx = g_rowptr[src] + atomicAdd(&g_cur[src], 1);
    g_ecsr[idx] = (src << 14) | (ty << 11) | dst;
}

// ---------------------------------------------------------------------------
// Fused centrality + LayerNorm1: h += emb; xn = LN(h)
// ---------------------------------------------------------------------------
__global__ __launch_bounds__(256)
void centrality_ln_kernel(const float* __restrict__ din_e,
                          const float* __restrict__ dout_e,
                          const float* __restrict__ gw,
                          const float* __restrict__ bw) {
    int n = blockIdx.x, tid = threadIdx.x;
    __shared__ float sh[9];
    int di = min(g_din[n],  MAXDEG);
    int dn = min(g_dout[n], MAXDEG);
    float x = g_h[n * DMODEL + tid]
            + din_e [(size_t)di * DMODEL + tid]
            + dout_e[(size_t)dn * DMODEL + tid];
    g_h[n * DMODEL + tid] = x;
    float v = x;
    #pragma unroll
    for (int o = 16; o >= 1; o >>= 1) v += __shfl_xor_sync(0xffffffffu, v, o);
    if ((tid & 31) == 0) sh[tid >> 5] = v;
    __syncthreads();
    if (tid == 0) {
        float s = 0.f;
        #pragma unroll
        for (int w = 0; w < 8; w++) s += sh[w];
        sh[8] = s * (1.0f / DMODEL);
    }
    __syncthreads();
    float mu = sh[8];
    float d = x - mu;
    v = d * d;
    #pragma unroll
    for (int o = 16; o >= 1; o >>= 1) v += __shfl_xor_sync(0xffffffffu, v, o);
    __syncthreads();
    if ((tid & 31) == 0) sh[tid >> 5] = v;
    __syncthreads();
    if (tid == 0) {
        float s = 0.f;
        #pragma unroll
        for (int w = 0; w < 8; w++) s += sh[w];
        sh[8] = s * (1.0f / DMODEL);
    }
    __syncthreads();
    float var = sh[8];
    g_xn[n * DMODEL + tid] = d * rsqrtf(var + 1e-5f) * gw[tid] + bw[tid];
}

// Plain LayerNorm (LN2)
__global__ __launch_bounds__(256)
void layernorm_kernel(const float* __restrict__ in, float* __restrict__ out,
                      const float* __restrict__ gw, const float* __restrict__ bw) {
    int row = blockIdx.x, tid = threadIdx.x;
    __shared__ float sh[9];
    float x = in[row * DMODEL + tid];
    float v = x;
    #pragma unroll
    for (int o = 16; o >= 1; o >>= 1) v += __shfl_xor_sync(0xffffffffu, v, o);
    if ((tid & 31) == 0) sh[tid >> 5] = v;
    __syncthreads();
    if (tid == 0) {
        float s = 0.f;
        #pragma unroll
        for (int w = 0; w < 8; w++) s += sh[w];
        sh[8] = s * (1.0f / DMODEL);
    }
    __syncthreads();
    float mu = sh[8];
    float d = x - mu;
    v = d * d;
    #pragma unroll
    for (int o = 16; o >= 1; o >>= 1) v += __shfl_xor_sync(0xffffffffu, v, o);
    __syncthreads();
    if ((tid & 31) == 0) sh[tid >> 5] = v;
    __syncthreads();
    if (tid == 0) {
        float s = 0.f;
        #pragma unroll
        for (int w = 0; w < 8; w++) s += sh[w];
        sh[8] = s * (1.0f / DMODEL);
    }
    __syncthreads();
    float var = sh[8];
    out[row * DMODEL + tid] = d * rsqrtf(var + 1e-5f) * gw[tid] + bw[tid];
}

// ---------------------------------------------------------------------------
// SGEMM: BK=32, double-buffered smem, one sync per slab.
// Template BM in {64,32}; THREADS = BM*4; microtile always 4x4; BN=64.
// C = [R +] epi(A[M,K] @ B[K,N] + bias[N])
// ---------------------------------------------------------------------------
enum { EPI_NONE = 0, EPI_GELU = 1, EPI_RES = 2 };

template <int EPI, int BM>
__device__ __forceinline__
void sgemm_body(const float* __restrict__ A, const float* __restrict__ B,
                const float* __restrict__ bias, const float* R,
                float* C, int M, int Nn, int K, int bx, int by) {
    constexpr int T   = BM * 4;
    constexpr int NB4 = 512 / T;      // B float4s per thread (2 or 4)
    __shared__ float As[2][32][BM];
    __shared__ float Bs[2][32][68];

    const int tid = threadIdx.x;
    const int tx = tid & 15, ty = tid >> 4;
    const int m0 = by * BM, n0 = bx * 64;

    // A loader indices (2 float4 per thread)
    int am[2], ak[2];
    #pragma unroll
    for (int v = 0; v < 2; v++) {
        int f = v * T + tid;           // float4 id over BM*8
        am[v] = f >> 3;
        ak[v] = (f & 7) << 2;
    }
    // B loader indices
    int bk[NB4], bn[NB4];
    #pragma unroll
    for (int v = 0; v < NB4; v++) {
        int f = v * T + tid;           // float4 id over 512
        bk[v] = f >> 4;
        bn[v] = (f & 15) << 2;
    }

    float acc[4][4];
    #pragma unroll
    for (int i = 0; i < 4; i++)
        #pragma unroll
        for (int j = 0; j < 4; j++) acc[i][j] = 0.f;

    float4 ra[2], rb[NB4];
    // prefetch slab 0
    #pragma unroll
    for (int v = 0; v < 2; v++)
        ra[v] = *(const float4*)(A + (size_t)(m0 + am[v]) * K + ak[v]);
    #pragma unroll
    for (int v = 0; v < NB4; v++)
        rb[v] = *(const float4*)(B + (size_t)bk[v] * Nn + n0 + bn[v]);
    // store slab 0
    #pragma unroll
    for (int v = 0; v < 2; v++) {
        As[0][ak[v] + 0][am[v]] = ra[v].x;
        As[0][ak[v] + 1][am[v]] = ra[v].y;
        As[0][ak[v] + 2][am[v]] = ra[v].z;
        As[0][ak[v] + 3][am[v]] = ra[v].w;
    }
    #pragma unroll
    for (int v = 0; v < NB4; v++)
        *(float4*)&Bs[0][bk[v]][bn[v]] = rb[v];
    __syncthreads();

    int cur = 0;
    for (int k0 = 0; k0 < K; k0 += 32) {
        const bool more = (k0 + 32 < K);
        if (more) {
            #pragma unroll
            for (int v = 0; v < 2; v++)
                ra[v] = *(const float4*)(A + (size_t)(m0 + am[v]) * K + k0 + 32 + ak[v]);
            #pragma unroll
            for (int v = 0; v < NB4; v++)
                rb[v] = *(const float4*)(B + (size_t)(k0 + 32 + bk[v]) * Nn + n0 + bn[v]);
        }
        const float (*Asc)[BM] = As[cur];
        const float (*Bsc)[68] = Bs[cur];
        #pragma unroll
        for (int k = 0; k < 32; k++) {
            float4 av = *(const float4*)&Asc[k][ty << 2];
            float4 bv = *(const float4*)&Bsc[k][tx << 2];
            float ar[4] = {av.x, av.y, av.z, av.w};
            float br[4] = {bv.x, bv.y, bv.z, bv.w};
            #pragma unroll
            for (int i = 0; i < 4; i++)
                #pragma unroll
                for (int j = 0; j < 4; j++)
                    acc[i][j] += ar[i] * br[j];
        }
        if (more) {
            int nxt = cur ^ 1;
            #pragma unroll
            for (int v = 0; v < 2; v++) {
                As[nxt][ak[v] + 0][am[v]] = ra[v].x;
                As[nxt][ak[v] + 1][am[v]] = ra[v].y;
                As[nxt][ak[v] + 2][am[v]] = ra[v].z;
                As[nxt][ak[v] + 3][am[v]] = ra[v].w;
            }
            #pragma unroll
            for (int v = 0; v < NB4; v++)
                *(float4*)&Bs[nxt][bk[v]][bn[v]] = rb[v];
        }
        __syncthreads();
        cur ^= 1;
    }

    float4 bv4 = *(const float4*)(bias + n0 + (tx << 2));
    float bb[4] = {bv4.x, bv4.y, bv4.z, bv4.w};
    #pragma unroll
    for (int i = 0; i < 4; i++) {
        int m = m0 + (ty << 2) + i;
        size_t off = (size_t)m * Nn + n0 + (tx << 2);
        float c[4];
        #pragma unroll
        for (int j = 0; j < 4; j++) {
            float val = acc[i][j] + bb[j];
            if (EPI == EPI_GELU) val = gelu_f(val);
            c[j] = val;
        }
        if (EPI == EPI_RES) {
            float4 r = *(const float4*)(R + off);
            c[0] += r.x; c[1] += r.y; c[2] += r.z; c[3] += r.w;
        }
        *(float4*)(C + off) = make_float4(c[0], c[1], c[2], c[3]);
    }
}

template <int EPI, int BM>
__global__ __launch_bounds__(BM * 4)
void sgemm_kernel(const float* __restrict__ A, const float* __restrict__ B,
                  const float* __restrict__ bias, const float* R,
                  float* C, int M, int Nn, int K) {
    sgemm_body<EPI, BM>(A, B, bias, R, C, M, Nn, K, blockIdx.x, blockIdx.y);
}

// Fused Q/K/V projection: grid (12, 32); blockIdx.x>>2 selects matrix.
__global__ __launch_bounds__(256)
void qkv_kernel(const float* __restrict__ xn,
                const float* __restrict__ Wq, const float* __restrict__ Wk,
                const float* __restrict__ Wv,
                const float* __restrict__ bq, const float* __restrict__ bk,
                const float* __restrict__ bv) {
    int which = blockIdx.x >> 2;
    int bx = blockIdx.x & 3;
    const float* B  = (which == 0) ? Wq : (which == 1) ? Wk : Wv;
    const float* bb = (which == 0) ? bq : (which == 1) ? bk : bv;
    float* C        = (which == 0) ? g_q : (which == 1) ? g_k : g_v;
    sgemm_body<EPI_NONE, 64>(xn, B, bb, nullptr, C, NNODE, DMODEL, DMODEL,
                             bx, blockIdx.y);
}

// ---------------------------------------------------------------------------
// Flash attention with fused bias (SPD gather from pos + CSR edge scatter).
// Block = (head, 64-row tile), 256 threads, dynamic smem.
// QK stage: 16x16 thread grid, 4x4 microtiles. Scores -> Ps (stride 68),
// edge smem scatter, streaming softmax, vectorized PV (float4 P & V loads).
// ---------------------------------------------------------------------------
#define PSTR 68

// dynamic smem layout (floats)
#define SM_QS   0                    // [32][68]
#define SM_KS   2176                 // [32][68]
#define SM_VS   4352                 // [64][36]
#define SM_PS   6656                 // [64][68]
#define SM_SE   11008                // unsigned [ECAP]
#define SM_CORR (11008 + ECAP)       // [64]
#define SM_L    (SM_CORR + 64)       // [64]
#define SM_STH  (SM_L + 64)          // [11]
#define SM_ETAB (SM_STH + 12)        // [8]
#define SM_TOTF (SM_ETAB + 8)
#define ATTN_SMEM_BYTES (SM_TOTF * 4)

__global__ __launch_bounds__(256)
void flash_attn3_kernel(const float* __restrict__ pos,
                        const float* __restrict__ spd_t,   // layer slice [11][8]
                        const float* __restrict__ edge_t)  // layer slice [8][8]
{
    extern __shared__ float sm[];
    float (*Qs)[68] = (float (*)[68])(sm + SM_QS);
    float (*Ks)[68] = (float (*)[68])(sm + SM_KS);
    float (*Vs)[36] = (float (*)[36])(sm + SM_VS);
    float* Ps    = sm + SM_PS;
    unsigned* Se = (unsigned*)(sm + SM_SE);
    float* corrS = sm + SM_CORR;
    float* lS    = sm + SM_L;
    float* sth   = sm + SM_STH;
    float* etab  = sm + SM_ETAB;

    const int h   = blockIdx.y;
    const int r0  = blockIdx.x * 64;
    const int tid = threadIdx.x;
    const int ty = tid >> 4, tx = tid & 15;     // QK mapping
    const int half = tid >> 7;                  // PV mapping
    const int t7 = tid & 127;
    const int pr = t7 >> 3, pc = t7 & 7;
    const float scale = 0.17677669529663687f;   // 1/sqrt(32)

    // per-head tables
    if (tid < 11)      sth[tid] = spd_t[tid * 8 + h];
    else if (tid < 19) etab[tid - 11] = edge_t[(tid - 11) * 8 + h];

    // block edge list (CSR rows r0..r0+63)
    const int eoff = g_rowptr[r0];
    const int cnt  = min(g_rowptr[r0 + 64] - eoff, ECAP);
    for (int i = tid; i < cnt; i += 256) Se[i] = g_ecsr[eoff + i];

    // Q tile, transposed + pre-scaled
    {
        int qr = tid >> 2;
        int qd = (tid & 3) << 3;
        const float* qp = g_q + (size_t)(r0 + qr) * DMODEL + h * DHEAD + qd;
        float4 q0 = *(const float4*)qp;
        float4 q1 = *(const float4*)(qp + 4);
        Qs[qd + 0][qr] = q0.x * scale; Qs[qd + 1][qr] = q0.y * scale;
        Qs[qd + 2][qr] = q0.z * scale; Qs[qd + 3][qr] = q0.w * scale;
        Qs[qd + 4][qr] = q1.x * scale; Qs[qd + 5][qr] = q1.y * scale;
        Qs[qd + 6][qr] = q1.z * scale; Qs[qd + 7][qr] = q1.w * scale;
    }

    float m[4], l[4], acc[4][4];
    #pragma unroll
    for (int i = 0; i < 4; i++) {
        m[i] = -1e30f; l[i] = 0.f;
        #pragma unroll
        for (int j = 0; j < 4; j++) acc[i][j] = 0.f;
    }

    for (int tile = 0; tile < NNODE / 64; tile++) {
        const int c0 = tile * 64;
        __syncthreads();   // Ks/Vs/Ps free (first iter: Qs/Se/tables ready)

        // K (transposed) and V tiles
        {
            int kr = tid >> 2;
            int kd = (tid & 3) << 3;
            const float* kp = g_k + (size_t)(c0 + kr) * DMODEL + h * DHEAD + kd;
            const float* vp = g_v + (size_t)(c0 + kr) * DMODEL + h * DHEAD + kd;
            float4 k0v = *(const float4*)kp;
            float4 k1v = *(const float4*)(kp + 4);
            float4 v0v = *(const float4*)vp;
            float4 v1v = *(const float4*)(vp + 4);
            Ks[kd + 0][kr] = k0v.x; Ks[kd + 1][kr] = k0v.y;
            Ks[kd + 2][kr] = k0v.z; Ks[kd + 3][kr] = k0v.w;
            Ks[kd + 4][kr] = k1v.x; Ks[kd + 5][kr] = k1v.y;
            Ks[kd + 6][kr] = k1v.z; Ks[kd + 7][kr] = k1v.w;
            *(float4*)&Vs[kr][kd]     = v0v;
            *(float4*)&Vs[kr][kd + 4] = v1v;
        }

        // SPD bias from pos (bucket inline)
        float s[4][4];
        #pragma unroll
        for (int i = 0; i < 4; i++) {
            const float* pp = pos + (size_t)(r0 + (ty << 2) + i) * NNODE + c0 + (tx << 2);
            float4 p4 = *(const float4*)pp;
            s[i][0] = sth[(int)fminf(fmaxf(p4.x * 10.0f + 0.5f, 0.0f), 10.0f)];
            s[i][1] = sth[(int)fminf(fmaxf(p4.y * 10.0f + 0.5f, 0.0f), 10.0f)];
            s[i][2] = sth[(int)fminf(fmaxf(p4.z * 10.0f + 0.5f, 0.0f), 10.0f)];
            s[i][3] = sth[(int)fminf(fmaxf(p4.w * 10.0f + 0.5f, 0.0f), 10.0f)];
        }
        __syncthreads();   // Ks/Vs visible

        // QK^T
        #pragma unroll
        for (int k = 0; k < 32; k++) {
            float4 av = *(const float4*)&Qs[k][ty << 2];
            float4 bv = *(const float4*)&Ks[k][tx << 2];
            float ar[4] = {av.x, av.y, av.z, av.w};
            float br[4] = {bv.x, bv.y, bv.z, bv.w};
            #pragma unroll
            for (int i = 0; i < 4; i++)
                #pragma unroll
                for (int j = 0; j < 4; j++)
                    acc_dummy: ;
            #pragma unroll
            for (int i = 0; i < 4; i++)
                #pragma unroll
                for (int j = 0; j < 4; j++)
                    s[i][j] += ar[i] * br[j];
        }

        // scores -> Ps
        #pragma unroll
        for (int i = 0; i < 4; i++) {
            int rloc = (ty << 2) + i;
            *(float4*)&Ps[rloc * PSTR + (tx << 2)] =
                make_float4(s[i][0], s[i][1], s[i][2], s[i][3]);
        }
        __syncthreads();

        // edge bias scatter (smem atomics)
        for (int i = tid; i < cnt; i += 256) {
            unsigned e = Se[i];
            unsigned d = (e & 0x7FFu) - (unsigned)c0;
            if (d < 64u)
                atomicAdd(&Ps[((e >> 14) - (unsigned)r0) * PSTR + d],
                          etab[(e >> 11) & 7u]);
        }
        __syncthreads();

        // read back + streaming softmax; write P
        #pragma unroll
        for (int i = 0; i < 4; i++) {
            int rloc = (ty << 2) + i;
            float4 s4 = *(const float4*)&Ps[rloc * PSTR + (tx << 2)];
            float tm = fmaxf(fmaxf(s4.x, s4.y), fmaxf(s4.z, s4.w));
            tm = fmaxf(tm, __shfl_xor_sync(0xffffffffu, tm, 1));
            tm = fmaxf(tm, __shfl_xor_sync(0xffffffffu, tm, 2));
            tm = fmaxf(tm, __shfl_xor_sync(0xffffffffu, tm, 4));
            tm = fmaxf(tm, __shfl_xor_sync(0xffffffffu, tm, 8));
            float mn = fmaxf(m[i], tm);
            float corr = __expf(m[i] - mn);
            m[i] = mn;
            float p0 = __expf(s4.x - mn);
            float p1 = __expf(s4.y - mn);
            float p2 = __expf(s4.z - mn);
            float p3 = __expf(s4.w - mn);
            float ls = p0 + p1 + p2 + p3;
            ls += __shfl_xor_sync(0xffffffffu, ls, 1);
            ls += __shfl_xor_sync(0xffffffffu, ls, 2);
            ls += __shfl_xor_sync(0xffffffffu, ls, 4);
            ls += __shfl_xor_sync(0xffffffffu, ls, 8);
            l[i] = l[i] * corr + ls;
            if (tx == 0) corrS[rloc] = corr;
            *(float4*)&Ps[rloc * PSTR + (tx << 2)] = make_float4(p0, p1, p2, p3);
        }
        __syncthreads();   // Ps(P) + corrS visible

        // P @ V (split-k over halves; vectorized P and V loads)
        {
            float cr[4];
            #pragma unroll
            for (int i = 0; i < 4; i++) cr[i] = corrS[(pr << 2) + i];
            #pragma unroll
            for (int i = 0; i < 4; i++)
                #pragma unroll
                for (int d = 0; d < 4; d++) acc[i][d] *= cr[i];
            const int jbase = half << 5;
            #pragma unroll
            for (int ch = 0; ch < 8; ch++) {
                const int j0 = jbase + (ch << 2);
                float p[4][4];
                #pragma unroll
                for (int i = 0; i < 4; i++) {
                    float4 p4 = *(const float4*)&Ps[((pr << 2) + i) * PSTR + j0];
                    p[i][0] = p4.x; p[i][1] = p4.y; p[i][2] = p4.z; p[i][3] = p4.w;
                }
                #pragma unroll
                for (int jv = 0; jv < 4; jv++) {
                    float4 v4 = *(const float4*)&Vs[j0 + jv][pc << 2];
                    #pragma unroll
                    for (int i = 0; i < 4; i++) {
                        acc[i][0] += p[i][jv] * v4.x;
                        acc[i][1] += p[i][jv] * v4.y;
                        acc[i][2] += p[i][jv] * v4.z;
                        acc[i][3] += p[i][jv] * v4.w;
                    }
                }
            }
        }
    }

    // Finalize: publish l, reduce halves via smem, normalize, write out
    if (tx == 0) {
        #pragma unroll
        for (int i = 0; i < 4; i++) lS[(ty << 2) + i] = l[i];
    }
    __syncthreads();
    float* obuf = Ps;   // reuse as [64][36]
    if (half == 1) {
        #pragma unroll
        for (int i = 0; i < 4; i++)
            *(float4*)&obuf[((pr << 2) + i) * 36 + (pc << 2)] =
                make_float4(acc[i][0], acc[i][1], acc[i][2], acc[i][3]);
    }
    __syncthreads();
    if (half == 0) {
        #pragma unroll
        for (int i = 0; i < 4; i++) {
            int rloc = (pr << 2) + i;
            float4 o = *(const float4*)&obuf[rloc * 36 + (pc << 2)];
            float inv = 1.0f / lS[rloc];
            *(float4*)(g_attn + (size_t)(r0 + rloc) * DMODEL + h * DHEAD + (pc << 2)) =
                make_float4((acc[i][0] + o.x) * inv, (acc[i][1] + o.y) * inv,
                            (acc[i][2] + o.z) * inv, (acc[i][3] + o.w) * inv);
        }
    }
}

// ---------------------------------------------------------------------------
// Host launch
// ---------------------------------------------------------------------------
extern "C" void kernel_launch(void* const* d_in, const int* in_sizes, int n_in,
                              void* d_out, int out_size) {
    const float* x     = (const float*)d_in[0];
    const int*   ei    = (const int*)  d_in[1];
    const int*   et    = (const int*)  d_in[2];
    const float* pos   = (const float*)d_in[3];
    const float* W_emb = (const float*)d_in[4];
    const float* b_emb = (const float*)d_in[5];
    const float* Wq    = (const float*)d_in[6];
    const float* Wk    = (const float*)d_in[7];
    const float* Wv    = (const float*)d_in[8];
    const float* Wo    = (const float*)d_in[9];
    const float* bq    = (const float*)d_in[10];
    const float* bk    = (const float*)d_in[11];
    const float* bv    = (const float*)d_in[12];
    const float* bo    = (const float*)d_in[13];
    const float* spd_t = (const float*)d_in[14];
    const float* edge_t= (const float*)d_in[15];
    const float* din_e = (const float*)d_in[16];
    const float* dout_e= (const float*)d_in[17];
    const float* ln1g  = (const float*)d_in[18];
    const float* ln1b  = (const float*)d_in[19];
    const float* ln2g  = (const float*)d_in[20];
    const float* ln2b  = (const float*)d_in[21];
    const float* W1    = (const float*)d_in[22];
    const float* b1    = (const float*)d_in[23];
    const float* W2    = (const float*)d_in[24];
    const float* b2    = (const float*)d_in[25];
    const float* Wout  = (const float*)d_in[26];
    const float* bout  = (const float*)d_in[27];
    float* out = (float*)d_out;

    float *p_h, *p_xn, *p_attn, *p_ffn;
    cudaGetSymbolAddress((void**)&p_h,    g_h);
    cudaGetSymbolAddress((void**)&p_xn,   g_xn);
    cudaGetSymbolAddress((void**)&p_attn, g_attn);
    cudaGetSymbolAddress((void**)&p_ffn,  g_ffn);

    static bool attr_set = false;
    if (!attr_set) {
        cudaFuncSetAttribute(flash_attn3_kernel,
                             cudaFuncAttributeMaxDynamicSharedMemorySize,
                             ATTN_SMEM_BYTES);
        attr_set = true;
    }

    // Graph-structural precompute
    deg_zero_kernel<<<(NNODE + 255) / 256, 256>>>();
    deg_acc_kernel<<<(NEDGE + 255) / 256, 256>>>(ei);
    csr_scan_kernel<<<1, 256>>>();
    csr_scatter_kernel<<<(NEDGE + 255) / 256, 256>>>(ei, et);

    // Node embedding: h = x @ W_emb + b_emb
    sgemm_kernel<EPI_NONE, 32><<<dim3(DMODEL / 64, NNODE / 32), 128>>>(
        x, W_emb, b_emb, nullptr, p_h, NNODE, DMODEL, DFEAT);

    for (int l = 0; l < 2; l++) {
        centrality_ln_kernel<<<NNODE, 256>>>(
            din_e + (size_t)l * 513 * DMODEL, dout_e + (size_t)l * 513 * DMODEL,
            ln1g + l * DMODEL, ln1b + l * DMODEL);
        qkv_kernel<<<dim3(12, NNODE / 64), 256>>>(
            p_xn,
            Wq + (size_t)l * DMODEL * DMODEL,
            Wk + (size_t)l * DMODEL * DMODEL,
            Wv + (size_t)l * DMODEL * DMODEL,
            bq + l * DMODEL, bk + l * DMODEL, bv + l * DMODEL);
        flash_attn3_kernel<<<dim3(NNODE / 64, NHEAD), 256, ATTN_SMEM_BYTES>>>(
            pos, spd_t + l * 88, edge_t + l * 64);
        sgemm_kernel<EPI_RES, 32><<<dim3(DMODEL / 64, NNODE / 32), 128>>>(
            p_attn, Wo + (size_t)l * DMODEL * DMODEL, bo + l * DMODEL, p_h, p_h,
            NNODE, DMODEL, DMODEL);
        layernorm_kernel<<<NNODE, 256>>>(p_h, p_xn, ln2g + l * DMODEL, ln2b + l * DMODEL);
        sgemm_kernel<EPI_GELU, 64><<<dim3(DFF / 64, NNODE / 64), 256>>>(
            p_xn, W1 + (size_t)l * DMODEL * DFF, b1 + l * DFF, nullptr, p_ffn,
            NNODE, DFF, DMODEL);
        sgemm_kernel<EPI_RES, 32><<<dim3(DMODEL / 64, NNODE / 32), 128>>>(
            p_ffn, W2 + (size_t)l * DFF * DMODEL, b2 + l * DMODEL, p_h, p_h,
            NNODE, DMODEL, DFF);
    }

    // output head
    sgemm_kernel<EPI_NONE, 32><<<dim3(DOUTF / 64, NNODE / 32), 128>>>(
        p_h, Wout, bout, nullptr, out, NNODE, DOUTF, DMODEL);
}

// round 14
// speedup vs baseline: 1.0668x; 1.0668x over previous
#include <cuda_runtime.h>
#include <math.h>

// ---------------------------------------------------------------------------
// Problem constants
// ---------------------------------------------------------------------------
#define NNODE   2048
#define DMODEL  256
#define NHEAD   8
#define DHEAD   32
#define NEDGE   65536
#define DFF     1024
#define DFEAT   128
#define DOUTF   128
#define MAXDEG  512
#define NN_TOT  (2048u*2048u)   // N*N
#define ECAP    4096            // max edges per 64-row block (mean 2048, sd ~45)

// ---------------------------------------------------------------------------
// Scratch (device globals; no dynamic allocation allowed)
// ---------------------------------------------------------------------------
__device__ float g_h   [NNODE*DMODEL];
__device__ float g_xn  [NNODE*DMODEL];
__device__ float g_q   [NNODE*DMODEL];
__device__ float g_k   [NNODE*DMODEL];
__device__ float g_v   [NNODE*DMODEL];
__device__ float g_attn[NNODE*DMODEL];
__device__ float g_ffn [NNODE*DFF];
__device__ int   g_din [NNODE];
__device__ int   g_dout[NNODE];
__device__ int   g_rowptr[NNODE + 1];
__device__ int   g_cur [NNODE];
__device__ unsigned g_ecsr[NEDGE];        // packed (src<<14)|(type<<11)|dst
__device__ unsigned g_sbu [NN_TOT / 4];   // SPD buckets, 4 x uchar packed

// ---------------------------------------------------------------------------
// Helpers
// ---------------------------------------------------------------------------
__device__ __forceinline__ float gelu_f(float x) {
    return 0.5f * x * (1.0f + erff(x * 0.70710678118654752440f));
}

// ---------------------------------------------------------------------------
// SPD bucket precompute: packed uchar4 per 4 columns
// ---------------------------------------------------------------------------
__global__ void spdb_kernel(const float* __restrict__ pos) {
    unsigned idx = blockIdx.x * blockDim.x + threadIdx.x; // over N*N/4
    if (idx >= NN_TOT / 4) return;
    float4 p = ((const float4*)pos)[idx];
    unsigned b0 = (unsigned)fminf(fmaxf(p.x * 10.0f + 0.5f, 0.0f), 10.0f);
    unsigned b1 = (unsigned)fminf(fmaxf(p.y * 10.0f + 0.5f, 0.0f), 10.0f);
    unsigned b2 = (unsigned)fminf(fmaxf(p.z * 10.0f + 0.5f, 0.0f), 10.0f);
    unsigned b3 = (unsigned)fminf(fmaxf(p.w * 10.0f + 0.5f, 0.0f), 10.0f);
    g_sbu[idx] = b0 | (b1 << 8) | (b2 << 16) | (b3 << 24);
}

// ---------------------------------------------------------------------------
// Degrees
// ---------------------------------------------------------------------------
__global__ void deg_zero_kernel() {
    int i = blockIdx.x * blockDim.x + threadIdx.x;
    if (i < NNODE) { g_din[i] = 0; g_dout[i] = 0; }
}
__global__ void deg_acc_kernel(const int* __restrict__ ei) {
    int e = blockIdx.x * blockDim.x + threadIdx.x;
    if (e >= NEDGE) return;
    atomicAdd(&g_dout[ei[e]], 1);          // src -> out-degree
    atomicAdd(&g_din [ei[NEDGE + e]], 1);  // dst -> in-degree
}

// ---------------------------------------------------------------------------
// CSR build: exclusive scan of out-degree (1 block, 256 thr x 8 vals)
// ---------------------------------------------------------------------------
__global__ __launch_bounds__(256)
void csr_scan_kernel() {
    __shared__ int ws[8];
    int t = threadIdx.x;
    int base = t * 8;
    int v[8];
    int tsum = 0;
    #pragma unroll
    for (int i = 0; i < 8; i++) { v[i] = g_dout[base + i]; tsum += v[i]; }
    int lane = t & 31, w = t >> 5;
    int inc = tsum;
    #pragma unroll
    for (int o = 1; o < 32; o <<= 1) {
        int n = __shfl_up_sync(0xffffffffu, inc, o);
        if (lane >= o) inc += n;
    }
    if (lane == 31) ws[w] = inc;
    __syncthreads();
    if (t == 0) {
        int run = 0;
        #pragma unroll
        for (int i = 0; i < 8; i++) { int tmp = ws[i]; ws[i] = run; run += tmp; }
    }
    __syncthreads();
    int run = inc - tsum + ws[w];   // exclusive prefix for this thread
    #pragma unroll
    for (int i = 0; i < 8; i++) {
        g_rowptr[base + i] = run;
        g_cur[base + i] = 0;
        run += v[i];
    }
    if (t == 255) g_rowptr[NNODE] = run;
}

__global__ void csr_scatter_kernel(const int* __restrict__ ei,
                                   const int* __restrict__ et) {
    int e = blockIdx.x * blockDim.x + threadIdx.x;
    if (e >= NEDGE) return;
    unsigned src = (unsigned)ei[e];
    unsigned dst = (unsigned)ei[NEDGE + e];
    unsigned ty  = (unsigned)et[e];
    int idx = g_rowptr[src] + atomicAdd(&g_cur[src], 1);
    g_ecsr[idx] = (src << 14) | (ty << 11) | dst;
}

// ---------------------------------------------------------------------------
// Fused centrality + LayerNorm1: h += emb; xn = LN(h)
// ---------------------------------------------------------------------------
__global__ __launch_bounds__(256)
void centrality_ln_kernel(const float* __restrict__ din_e,
                          const float* __restrict__ dout_e,
                          const float* __restrict__ gw,
                          const float* __restrict__ bw) {
    int n = blockIdx.x, tid = threadIdx.x;
    __shared__ float sh[9];
    int di = min(g_din[n],  MAXDEG);
    int dn = min(g_dout[n], MAXDEG);
    float x = g_h[n * DMODEL + tid]
            + din_e [(size_t)di * DMODEL + tid]
            + dout_e[(size_t)dn * DMODEL + tid];
    g_h[n * DMODEL + tid] = x;
    float v = x;
    #pragma unroll
    for (int o = 16; o >= 1; o >>= 1) v += __shfl_xor_sync(0xffffffffu, v, o);
    if ((tid & 31) == 0) sh[tid >> 5] = v;
    __syncthreads();
    if (tid == 0) {
        float s = 0.f;
        #pragma unroll
        for (int w = 0; w < 8; w++) s += sh[w];
        sh[8] = s * (1.0f / DMODEL);
    }
    __syncthreads();
    float mu = sh[8];
    float d = x - mu;
    v = d * d;
    #pragma unroll
    for (int o = 16; o >= 1; o >>= 1) v += __shfl_xor_sync(0xffffffffu, v, o);
    __syncthreads();
    if ((tid & 31) == 0) sh[tid >> 5] = v;
    __syncthreads();
    if (tid == 0) {
        float s = 0.f;
        #pragma unroll
        for (int w = 0; w < 8; w++) s += sh[w];
        sh[8] = s * (1.0f / DMODEL);
    }
    __syncthreads();
    float var = sh[8];
    g_xn[n * DMODEL + tid] = d * rsqrtf(var + 1e-5f) * gw[tid] + bw[tid];
}

// Plain LayerNorm (LN2)
__global__ __launch_bounds__(256)
void layernorm_kernel(const float* __restrict__ in, float* __restrict__ out,
                      const float* __restrict__ gw, const float* __restrict__ bw) {
    int row = blockIdx.x, tid = threadIdx.x;
    __shared__ float sh[9];
    float x = in[row * DMODEL + tid];
    float v = x;
    #pragma unroll
    for (int o = 16; o >= 1; o >>= 1) v += __shfl_xor_sync(0xffffffffu, v, o);
    if ((tid & 31) == 0) sh[tid >> 5] = v;
    __syncthreads();
    if (tid == 0) {
        float s = 0.f;
        #pragma unroll
        for (int w = 0; w < 8; w++) s += sh[w];
        sh[8] = s * (1.0f / DMODEL);
    }
    __syncthreads();
    float mu = sh[8];
    float d = x - mu;
    v = d * d;
    #pragma unroll
    for (int o = 16; o >= 1; o >>= 1) v += __shfl_xor_sync(0xffffffffu, v, o);
    __syncthreads();
    if ((tid & 31) == 0) sh[tid >> 5] = v;
    __syncthreads();
    if (tid == 0) {
        float s = 0.f;
        #pragma unroll
        for (int w = 0; w < 8; w++) s += sh[w];
        sh[8] = s * (1.0f / DMODEL);
    }
    __syncthreads();
    float var = sh[8];
    out[row * DMODEL + tid] = d * rsqrtf(var + 1e-5f) * gw[tid] + bw[tid];
}

// ---------------------------------------------------------------------------
// SGEMM: BK=32, double-buffered smem, one sync per slab.
// Template BM in {64,32}; THREADS = BM*4; microtile always 4x4; BN=64.
// C = [R +] epi(A[M,K] @ B[K,N] + bias[N])
// ---------------------------------------------------------------------------
enum { EPI_NONE = 0, EPI_GELU = 1, EPI_RES = 2 };

template <int EPI, int BM>
__device__ __forceinline__
void sgemm_body(const float* __restrict__ A, const float* __restrict__ B,
                const float* __restrict__ bias, const float* R,
                float* C, int M, int Nn, int K, int bx, int by) {
    constexpr int T   = BM * 4;
    constexpr int NB4 = 512 / T;      // B float4s per thread (2 or 4)
    __shared__ float As[2][32][BM];
    __shared__ float Bs[2][32][68];

    const int tid = threadIdx.x;
    const int tx = tid & 15, ty = tid >> 4;
    const int m0 = by * BM, n0 = bx * 64;

    int am[2], ak[2];
    #pragma unroll
    for (int v = 0; v < 2; v++) {
        int f = v * T + tid;
        am[v] = f >> 3;
        ak[v] = (f & 7) << 2;
    }
    int bk[NB4], bn[NB4];
    #pragma unroll
    for (int v = 0; v < NB4; v++) {
        int f = v * T + tid;
        bk[v] = f >> 4;
        bn[v] = (f & 15) << 2;
    }

    float acc[4][4];
    #pragma unroll
    for (int i = 0; i < 4; i++)
        #pragma unroll
        for (int j = 0; j < 4; j++) acc[i][j] = 0.f;

    float4 ra[2], rb[NB4];
    #pragma unroll
    for (int v = 0; v < 2; v++)
        ra[v] = *(const float4*)(A + (size_t)(m0 + am[v]) * K + ak[v]);
    #pragma unroll
    for (int v = 0; v < NB4; v++)
        rb[v] = *(const float4*)(B + (size_t)bk[v] * Nn + n0 + bn[v]);
    #pragma unroll
    for (int v = 0; v < 2; v++) {
        As[0][ak[v] + 0][am[v]] = ra[v].x;
        As[0][ak[v] + 1][am[v]] = ra[v].y;
        As[0][ak[v] + 2][am[v]] = ra[v].z;
        As[0][ak[v] + 3][am[v]] = ra[v].w;
    }
    #pragma unroll
    for (int v = 0; v < NB4; v++)
        *(float4*)&Bs[0][bk[v]][bn[v]] = rb[v];
    __syncthreads();

    int cur = 0;
    for (int k0 = 0; k0 < K; k0 += 32) {
        const bool more = (k0 + 32 < K);
        if (more) {
            #pragma unroll
            for (int v = 0; v < 2; v++)
                ra[v] = *(const float4*)(A + (size_t)(m0 + am[v]) * K + k0 + 32 + ak[v]);
            #pragma unroll
            for (int v = 0; v < NB4; v++)
                rb[v] = *(const float4*)(B + (size_t)(k0 + 32 + bk[v]) * Nn + n0 + bn[v]);
        }
        const float (*Asc)[BM] = As[cur];
        const float (*Bsc)[68] = Bs[cur];
        #pragma unroll
        for (int k = 0; k < 32; k++) {
            float4 av = *(const float4*)&Asc[k][ty << 2];
            float4 bv = *(const float4*)&Bsc[k][tx << 2];
            float ar[4] = {av.x, av.y, av.z, av.w};
            float br[4] = {bv.x, bv.y, bv.z, bv.w};
            #pragma unroll
            for (int i = 0; i < 4; i++)
                #pragma unroll
                for (int j = 0; j < 4; j++)
                    acc[i][j] += ar[i] * br[j];
        }
        if (more) {
            int nxt = cur ^ 1;
            #pragma unroll
            for (int v = 0; v < 2; v++) {
                As[nxt][ak[v] + 0][am[v]] = ra[v].x;
                As[nxt][ak[v] + 1][am[v]] = ra[v].y;
                As[nxt][ak[v] + 2][am[v]] = ra[v].z;
                As[nxt][ak[v] + 3][am[v]] = ra[v].w;
            }
            #pragma unroll
            for (int v = 0; v < NB4; v++)
                *(float4*)&Bs[nxt][bk[v]][bn[v]] = rb[v];
        }
        __syncthreads();
        cur ^= 1;
    }

    float4 bv4 = *(const float4*)(bias + n0 + (tx << 2));
    float bb[4] = {bv4.x, bv4.y, bv4.z, bv4.w};
    #pragma unroll
    for (int i = 0; i < 4; i++) {
        int m = m0 + (ty << 2) + i;
        size_t off = (size_t)m * Nn + n0 + (tx << 2);
        float c[4];
        #pragma unroll
        for (int j = 0; j < 4; j++) {
            float val = acc[i][j] + bb[j];
            if (EPI == EPI_GELU) val = gelu_f(val);
            c[j] = val;
        }
        if (EPI == EPI_RES) {
            float4 r = *(const float4*)(R + off);
            c[0] += r.x; c[1] += r.y; c[2] += r.z; c[3] += r.w;
        }
        *(float4*)(C + off) = make_float4(c[0], c[1], c[2], c[3]);
    }
}

template <int EPI, int BM>
__global__ __launch_bounds__(BM * 4)
void sgemm_kernel(const float* __restrict__ A, const float* __restrict__ B,
                  const float* __restrict__ bias, const float* R,
                  float* C, int M, int Nn, int K) {
    sgemm_body<EPI, BM>(A, B, bias, R, C, M, Nn, K, blockIdx.x, blockIdx.y);
}

// Fused Q/K/V projection: grid (12, 32); blockIdx.x>>2 selects matrix.
__global__ __launch_bounds__(256)
void qkv_kernel(const float* __restrict__ xn,
                const float* __restrict__ Wq, const float* __restrict__ Wk,
                const float* __restrict__ Wv,
                const float* __restrict__ bq, const float* __restrict__ bk,
                const float* __restrict__ bv) {
    int which = blockIdx.x >> 2;
    int bx = blockIdx.x & 3;
    const float* B  = (which == 0) ? Wq : (which == 1) ? Wk : Wv;
    const float* bb = (which == 0) ? bq : (which == 1) ? bk : bv;
    float* C        = (which == 0) ? g_q : (which == 1) ? g_k : g_v;
    sgemm_body<EPI_NONE, 64>(xn, B, bb, nullptr, C, NNODE, DMODEL, DMODEL,
                             bx, blockIdx.y);
}

// ---------------------------------------------------------------------------
// Flash attention v4: no-max single-pass softmax, scatter-first edge bias,
// per-block counting sort of the edge list by dst tile, packed SPD buckets.
// Block = (head, 64-row tile), 256 threads, dynamic smem. 4 syncs / tile.
// ---------------------------------------------------------------------------
#define PSTR 68

// dynamic smem layout (float offsets)
#define SM_QS   0                        // [32][68] = 2176
#define SM_KS   2176                     // [32][68]
#define SM_VS   4352                     // [64][36] = 2304
#define SM_PS   6656                     // [64][68] = 4352
#define SM_SE   11008                    // unsigned [ECAP]
#define SM_LS   (SM_SE + ECAP)           // [64]
#define SM_STH  (SM_LS + 64)             // [11] (pad 12)
#define SM_ETAB (SM_STH + 12)            // [8]
#define SM_BCNT (SM_ETAB + 8)            // int [32]
#define SM_BOFF (SM_BCNT + 32)           // int [33]
#define SM_BCUR (SM_BOFF + 33)           // int [32]
#define SM_TOTF (SM_BCUR + 32)
#define ATTN_SMEM_BYTES (SM_TOTF * 4)

__global__ __launch_bounds__(256)
void flash_attn4_kernel(const float* __restrict__ spd_t,   // layer slice [11][8]
                        const float* __restrict__ edge_t)  // layer slice [8][8]
{
    extern __shared__ float sm[];
    float (*Qs)[68] = (float (*)[68])(sm + SM_QS);
    float (*Ks)[68] = (float (*)[68])(sm + SM_KS);
    float (*Vs)[36] = (float (*)[36])(sm + SM_VS);
    float* Ps    = sm + SM_PS;
    unsigned* Se = (unsigned*)(sm + SM_SE);
    float* lS    = sm + SM_LS;
    float* sth   = sm + SM_STH;
    float* etab  = sm + SM_ETAB;
    int* bcnt    = (int*)(sm + SM_BCNT);
    int* boff    = (int*)(sm + SM_BOFF);
    int* bcur    = (int*)(sm + SM_BCUR);

    const int h   = blockIdx.y;
    const int r0  = blockIdx.x * 64;
    const int tid = threadIdx.x;
    const int ty = tid >> 4, tx = tid & 15;     // QK mapping
    const int half = tid >> 7;                  // PV mapping
    const int t7 = tid & 127;
    const int pr = t7 >> 3, pc = t7 & 7;
    const float scale = 0.17677669529663687f;   // 1/sqrt(32)

    // per-head tables + bucket counters
    if (tid < 11)      sth[tid] = spd_t[tid * 8 + h];
    else if (tid < 19) etab[tid - 11] = edge_t[(tid - 11) * 8 + h];
    if (tid < 32) bcnt[tid] = 0;
    __syncthreads();

    // counting sort of this row-block's edges by dst tile
    const int eoff = g_rowptr[r0];
    const int cnt  = min(g_rowptr[r0 + 64] - eoff, ECAP);
    for (int i = tid; i < cnt; i += 256)
        atomicAdd(&bcnt[(g_ecsr[eoff + i] & 0x7FFu) >> 6], 1);
    __syncthreads();
    if (tid == 0) {
        int run = 0;
        #pragma unroll
        for (int b = 0; b < 32; b++) { boff[b] = run; run += bcnt[b]; }
        boff[32] = run;
    }
    __syncthreads();
    if (tid < 32) bcur[tid] = boff[tid];
    __syncthreads();
    for (int i = tid; i < cnt; i += 256) {
        unsigned e = g_ecsr[eoff + i];
        int b = (e & 0x7FFu) >> 6;
        Se[atomicAdd(&bcur[b], 1)] = e;
    }

    // Q tile, transposed + pre-scaled
    {
        int qr = tid >> 2;
        int qd = (tid & 3) << 3;
        const float* qp = g_q + (size_t)(r0 + qr) * DMODEL + h * DHEAD + qd;
        float4 q0 = *(const float4*)qp;
        float4 q1 = *(const float4*)(qp + 4);
        Qs[qd + 0][qr] = q0.x * scale; Qs[qd + 1][qr] = q0.y * scale;
        Qs[qd + 2][qr] = q0.z * scale; Qs[qd + 3][qr] = q0.w * scale;
        Qs[qd + 4][qr] = q1.x * scale; Qs[qd + 5][qr] = q1.y * scale;
        Qs[qd + 6][qr] = q1.z * scale; Qs[qd + 7][qr] = q1.w * scale;
    }

    float l[4], acc[4][4];
    #pragma unroll
    for (int i = 0; i < 4; i++) {
        l[i] = 0.f;
        #pragma unroll
        for (int j = 0; j < 4; j++) acc[i][j] = 0.f;
    }

    for (int tile = 0; tile < NNODE / 64; tile++) {
        const int c0 = tile * 64;
        __syncthreads();   // Ps/Ks/Vs free (first iter: Se/boff/Qs ready)

        // zero Ps (scatter target) + load K/V tiles
        {
            float4 z4 = make_float4(0.f, 0.f, 0.f, 0.f);
            for (int v = tid; v < (64 * PSTR) / 4; v += 256)
                ((float4*)Ps)[v] = z4;
        }
        {
            int kr = tid >> 2;
            int kd = (tid & 3) << 3;
            const float* kp = g_k + (size_t)(c0 + kr) * DMODEL + h * DHEAD + kd;
            const float* vp = g_v + (size_t)(c0 + kr) * DMODEL + h * DHEAD + kd;
            float4 k0v = *(const float4*)kp;
            float4 k1v = *(const float4*)(kp + 4);
            float4 v0v = *(const float4*)vp;
            float4 v1v = *(const float4*)(vp + 4);
            Ks[kd + 0][kr] = k0v.x; Ks[kd + 1][kr] = k0v.y;
            Ks[kd + 2][kr] = k0v.z; Ks[kd + 3][kr] = k0v.w;
            Ks[kd + 4][kr] = k1v.x; Ks[kd + 5][kr] = k1v.y;
            Ks[kd + 6][kr] = k1v.z; Ks[kd + 7][kr] = k1v.w;
            *(float4*)&Vs[kr][kd]     = v0v;
            *(float4*)&Vs[kr][kd + 4] = v1v;
        }
        __syncthreads();   // Ps zeroed, K/V ready

        // edge bias scatter (only this tile's bucket)
        {
            int s0 = boff[tile], s1 = boff[tile + 1];
            for (int i = s0 + tid; i < s1; i += 256) {
                unsigned e = Se[i];
                atomicAdd(&Ps[((e >> 14) - (unsigned)r0) * PSTR + (e & 63u)],
                          etab[(e >> 11) & 7u]);
            }
        }
        __syncthreads();   // edge bias in Ps

        // QK^T with SPD (packed buckets) + edge bias; single-pass exp
        float s[4][4];
        #pragma unroll
        for (int i = 0; i < 4; i++) {
            int rloc = (ty << 2) + i;
            float4 eb = *(const float4*)&Ps[rloc * PSTR + (tx << 2)];
            unsigned bk4 = g_sbu[((size_t)(r0 + rloc) * NNODE + c0 + (tx << 2)) >> 2];
            s[i][0] = eb.x + sth[bk4 & 255u];
            s[i][1] = eb.y + sth[(bk4 >> 8) & 255u];
            s[i][2] = eb.z + sth[(bk4 >> 16) & 255u];
            s[i][3] = eb.w + sth[bk4 >> 24];
        }
        #pragma unroll
        for (int k = 0; k < 32; k++) {
            float4 av = *(const float4*)&Qs[k][ty << 2];
            float4 bv = *(const float4*)&Ks[k][tx << 2];
            float ar[4] = {av.x, av.y, av.z, av.w};
            float br[4] = {bv.x, bv.y, bv.z, bv.w};
            #pragma unroll
            for (int i = 0; i < 4; i++)
                #pragma unroll
                for (int j = 0; j < 4; j++)
                    s[i][j] += ar[i] * br[j];
        }
        #pragma unroll
        for (int i = 0; i < 4; i++) {
            int rloc = (ty << 2) + i;
            float p0 = __expf(s[i][0]);
            float p1 = __expf(s[i][1]);
            float p2 = __expf(s[i][2]);
            float p3 = __expf(s[i][3]);
            l[i] += p0 + p1 + p2 + p3;
            *(float4*)&Ps[rloc * PSTR + (tx << 2)] = make_float4(p0, p1, p2, p3);
        }
        __syncthreads();   // P ready

        // P @ V (split-k over halves; vectorized P and V loads, no corr)
        {
            const int jbase = half << 5;
            #pragma unroll
            for (int ch = 0; ch < 8; ch++) {
                const int j0 = jbase + (ch << 2);
                float p[4][4];
                #pragma unroll
                for (int i = 0; i < 4; i++) {
                    float4 p4 = *(const float4*)&Ps[((pr << 2) + i) * PSTR + j0];
                    p[i][0] = p4.x; p[i][1] = p4.y; p[i][2] = p4.z; p[i][3] = p4.w;
                }
                #pragma unroll
                for (int jv = 0; jv < 4; jv++) {
                    float4 v4 = *(const float4*)&Vs[j0 + jv][pc << 2];
                    #pragma unroll
                    for (int i = 0; i < 4; i++) {
                        acc[i][0] += p[i][jv] * v4.x;
                        acc[i][1] += p[i][jv] * v4.y;
                        acc[i][2] += p[i][jv] * v4.z;
                        acc[i][3] += p[i][jv] * v4.w;
                    }
                }
            }
        }
    }

    // Reduce l across the 16 tx lanes (once), publish
    #pragma unroll
    for (int i = 0; i < 4; i++) {
        float v = l[i];
        v += __shfl_xor_sync(0xffffffffu, v, 1);
        v += __shfl_xor_sync(0xffffffffu, v, 2);
        v += __shfl_xor_sync(0xffffffffu, v, 4);
        v += __shfl_xor_sync(0xffffffffu, v, 8);
        l[i] = v;
    }
    __syncthreads();
    if (tx == 0) {
        #pragma unroll
        for (int i = 0; i < 4; i++) lS[(ty << 2) + i] = l[i];
    }
    __syncthreads();

    // Reduce halves via smem, normalize, write out
    float* obuf = Ps;   // reuse as [64][36]
    if (half == 1) {
        #pragma unroll
        for (int i = 0; i < 4; i++)
            *(float4*)&obuf[((pr << 2) + i) * 36 + (pc << 2)] =
                make_float4(acc[i][0], acc[i][1], acc[i][2], acc[i][3]);
    }
    __syncthreads();
    if (half == 0) {
        #pragma unroll
        for (int i = 0; i < 4; i++) {
            int rloc = (pr << 2) + i;
            float4 o = *(const float4*)&obuf[rloc * 36 + (pc << 2)];
            float inv = 1.0f / lS[rloc];
            *(float4*)(g_attn + (size_t)(r0 + rloc) * DMODEL + h * DHEAD + (pc << 2)) =
                make_float4((acc[i][0] + o.x) * inv, (acc[i][1] + o.y) * inv,
                            (acc[i][2] + o.z) * inv, (acc[i][3] + o.w) * inv);
        }
    }
}

// ---------------------------------------------------------------------------
// Host launch
// ---------------------------------------------------------------------------
extern "C" void kernel_launch(void* const* d_in, const int* in_sizes, int n_in,
                              void* d_out, int out_size) {
    const float* x     = (const float*)d_in[0];
    const int*   ei    = (const int*)  d_in[1];
    const int*   et    = (const int*)  d_in[2];
    const float* pos   = (const float*)d_in[3];
    const float* W_emb = (const float*)d_in[4];
    const float* b_emb = (const float*)d_in[5];
    const float* Wq    = (const float*)d_in[6];
    const float* Wk    = (const float*)d_in[7];
    const float* Wv    = (const float*)d_in[8];
    const float* Wo    = (const float*)d_in[9];
    const float* bq    = (const float*)d_in[10];
    const float* bk    = (const float*)d_in[11];
    const float* bv    = (const float*)d_in[12];
    const float* bo    = (const float*)d_in[13];
    const float* spd_t = (const float*)d_in[14];
    const float* edge_t= (const float*)d_in[15];
    const float* din_e = (const float*)d_in[16];
    const float* dout_e= (const float*)d_in[17];
    const float* ln1g  = (const float*)d_in[18];
    const float* ln1b  = (const float*)d_in[19];
    const float* ln2g  = (const float*)d_in[20];
    const float* ln2b  = (const float*)d_in[21];
    const float* W1    = (const float*)d_in[22];
    const float* b1    = (const float*)d_in[23];
    const float* W2    = (const float*)d_in[24];
    const float* b2    = (const float*)d_in[25];
    const float* Wout  = (const float*)d_in[26];
    const float* bout  = (const float*)d_in[27];
    float* out = (float*)d_out;

    float *p_h, *p_xn, *p_attn, *p_ffn;
    cudaGetSymbolAddress((void**)&p_h,    g_h);
    cudaGetSymbolAddress((void**)&p_xn,   g_xn);
    cudaGetSymbolAddress((void**)&p_attn, g_attn);
    cudaGetSymbolAddress((void**)&p_ffn,  g_ffn);

    // idempotent; called every launch (no static guards allowed)
    cudaFuncSetAttribute(flash_attn4_kernel,
                         cudaFuncAttributeMaxDynamicSharedMemorySize,
                         ATTN_SMEM_BYTES);

    // Graph-structural precompute
    spdb_kernel<<<(NN_TOT / 4 + 255) / 256, 256>>>(pos);
    deg_zero_kernel<<<(NNODE + 255) / 256, 256>>>();
    deg_acc_kernel<<<(NEDGE + 255) / 256, 256>>>(ei);
    csr_scan_kernel<<<1, 256>>>();
    csr_scatter_kernel<<<(NEDGE + 255) / 256, 256>>>(ei, et);

    // Node embedding: h = x @ W_emb + b_emb
    sgemm_kernel<EPI_NONE, 32><<<dim3(DMODEL / 64, NNODE / 32), 128>>>(
        x, W_emb, b_emb, nullptr, p_h, NNODE, DMODEL, DFEAT);

    for (int l = 0; l < 2; l++) {
        centrality_ln_kernel<<<NNODE, 256>>>(
            din_e + (size_t)l * 513 * DMODEL, dout_e + (size_t)l * 513 * DMODEL,
            ln1g + l * DMODEL, ln1b + l * DMODEL);
        qkv_kernel<<<dim3(12, NNODE / 64), 256>>>(
            p_xn,
            Wq + (size_t)l * DMODEL * DMODEL,
            Wk + (size_t)l * DMODEL * DMODEL,
            Wv + (size_t)l * DMODEL * DMODEL,
            bq + l * DMODEL, bk + l * DMODEL, bv + l * DMODEL);
        flash_attn4_kernel<<<dim3(NNODE / 64, NHEAD), 256, ATTN_SMEM_BYTES>>>(
            spd_t + l * 88, edge_t + l * 64);
        sgemm_kernel<EPI_RES, 32><<<dim3(DMODEL / 64, NNODE / 32), 128>>>(
            p_attn, Wo + (size_t)l * DMODEL * DMODEL, bo + l * DMODEL, p_h, p_h,
            NNODE, DMODEL, DMODEL);
        layernorm_kernel<<<NNODE, 256>>>(p_h, p_xn, ln2g + l * DMODEL, ln2b + l * DMODEL);
        sgemm_kernel<EPI_GELU, 64><<<dim3(DFF / 64, NNODE / 64), 256>>>(
            p_xn, W1 + (size_t)l * DMODEL * DFF, b1 + l * DFF, nullptr, p_ffn,
            NNODE, DFF, DMODEL);
        sgemm_kernel<EPI_RES, 32><<<dim3(DMODEL / 64, NNODE / 32), 128>>>(
            p_ffn, W2 + (size_t)l * DFF * DMODEL, b2 + l * DMODEL, p_h, p_h,
            NNODE, DMODEL, DFF);
    }

    // output head
    sgemm_kernel<EPI_NONE, 32><<<dim3(DOUTF / 64, NNODE / 32), 128>>>(
        p_h, Wout, bout, nullptr, out, NNODE, DOUTF, DMODEL);
}

// round 16
// speedup vs baseline: 1.3469x; 1.2626x over previous
#include <cuda_runtime.h>
#include <math.h>

// ---------------------------------------------------------------------------
// Problem constants
// ---------------------------------------------------------------------------
#define NNODE   2048
#define DMODEL  256
#define NHEAD   8
#define DHEAD   32
#define NEDGE   65536
#define DFF     1024
#define DFEAT   128
#define DOUTF   128
#define MAXDEG  512
#define NN_TOT  (2048u*2048u)   // N*N
#define ECAP    4096            // max edges per 64-row block (mean 2048, sd ~45)

// ---------------------------------------------------------------------------
// Scratch (device globals; no dynamic allocation allowed)
// ---------------------------------------------------------------------------
__device__ float g_h   [NNODE*DMODEL];
__device__ float g_xn  [NNODE*DMODEL];
__device__ float g_q   [NNODE*DMODEL];
__device__ float g_k   [NNODE*DMODEL];
__device__ float g_v   [NNODE*DMODEL];
__device__ float g_attn[NNODE*DMODEL];
__device__ float g_ffn [NNODE*DFF];
__device__ int   g_din [NNODE];
__device__ int   g_dout[NNODE];
__device__ int   g_rowptr[NNODE + 1];
__device__ int   g_cur [NNODE];
__device__ unsigned g_ecsr[NEDGE];        // packed (src<<14)|(type<<11)|dst
__device__ unsigned g_sbu [NN_TOT / 4];   // SPD buckets, 4 x uchar packed

// ---------------------------------------------------------------------------
// Helpers
// ---------------------------------------------------------------------------
__device__ __forceinline__ float gelu_f(float x) {
    return 0.5f * x * (1.0f + erff(x * 0.70710678118654752440f));
}

__device__ __forceinline__ unsigned f2tf(float x) {
    unsigned r;
    asm("cvt.rna.tf32.f32 %0, %1;" : "=r"(r) : "f"(x));
    return r;
}

__device__ __forceinline__ void mma_tf32(float* c, unsigned a0, unsigned a1,
                                         unsigned a2, unsigned a3,
                                         unsigned b0, unsigned b1) {
    asm volatile(
        "mma.sync.aligned.m16n8k8.row.col.f32.tf32.tf32.f32 "
        "{%0,%1,%2,%3}, {%4,%5,%6,%7}, {%8,%9}, {%0,%1,%2,%3};\n"
        : "+f"(c[0]), "+f"(c[1]), "+f"(c[2]), "+f"(c[3])
        : "r"(a0), "r"(a1), "r"(a2), "r"(a3), "r"(b0), "r"(b1));
}

// ---------------------------------------------------------------------------
// SPD bucket precompute: packed uchar4 per 4 columns
// ---------------------------------------------------------------------------
__global__ void spdb_kernel(const float* __restrict__ pos) {
    unsigned idx = blockIdx.x * blockDim.x + threadIdx.x; // over N*N/4
    if (idx >= NN_TOT / 4) return;
    float4 p = ((const float4*)pos)[idx];
    unsigned b0 = (unsigned)fminf(fmaxf(p.x * 10.0f + 0.5f, 0.0f), 10.0f);
    unsigned b1 = (unsigned)fminf(fmaxf(p.y * 10.0f + 0.5f, 0.0f), 10.0f);
    unsigned b2 = (unsigned)fminf(fmaxf(p.z * 10.0f + 0.5f, 0.0f), 10.0f);
    unsigned b3 = (unsigned)fminf(fmaxf(p.w * 10.0f + 0.5f, 0.0f), 10.0f);
    g_sbu[idx] = b0 | (b1 << 8) | (b2 << 16) | (b3 << 24);
}

// ---------------------------------------------------------------------------
// Degrees
// ---------------------------------------------------------------------------
__global__ void deg_zero_kernel() {
    int i = blockIdx.x * blockDim.x + threadIdx.x;
    if (i < NNODE) { g_din[i] = 0; g_dout[i] = 0; }
}
__global__ void deg_acc_kernel(const int* __restrict__ ei) {
    int e = blockIdx.x * blockDim.x + threadIdx.x;
    if (e >= NEDGE) return;
    atomicAdd(&g_dout[ei[e]], 1);          // src -> out-degree
    atomicAdd(&g_din [ei[NEDGE + e]], 1);  // dst -> in-degree
}

// ---------------------------------------------------------------------------
// CSR build: exclusive scan of out-degree (1 block, 256 thr x 8 vals)
// ---------------------------------------------------------------------------
__global__ __launch_bounds__(256)
void csr_scan_kernel() {
    __shared__ int ws[8];
    int t = threadIdx.x;
    int base = t * 8;
    int v[8];
    int tsum = 0;
    #pragma unroll
    for (int i = 0; i < 8; i++) { v[i] = g_dout[base + i]; tsum += v[i]; }
    int lane = t & 31, w = t >> 5;
    int inc = tsum;
    #pragma unroll
    for (int o = 1; o < 32; o <<= 1) {
        int n = __shfl_up_sync(0xffffffffu, inc, o);
        if (lane >= o) inc += n;
    }
    if (lane == 31) ws[w] = inc;
    __syncthreads();
    if (t == 0) {
        int run = 0;
        #pragma unroll
        for (int i = 0; i < 8; i++) { int tmp = ws[i]; ws[i] = run; run += tmp; }
    }
    __syncthreads();
    int run = inc - tsum + ws[w];   // exclusive prefix for this thread
    #pragma unroll
    for (int i = 0; i < 8; i++) {
        g_rowptr[base + i] = run;
        g_cur[base + i] = 0;
        run += v[i];
    }
    if (t == 255) g_rowptr[NNODE] = run;
}

__global__ void csr_scatter_kernel(const int* __restrict__ ei,
                                   const int* __restrict__ et) {
    int e = blockIdx.x * blockDim.x + threadIdx.x;
    if (e >= NEDGE) return;
    unsigned src = (unsigned)ei[e];
    unsigned dst = (unsigned)ei[NEDGE + e];
    unsigned ty  = (unsigned)et[e];
    int idx = g_rowptr[src] + atomicAdd(&g_cur[src], 1);
    g_ecsr[idx] = (src << 14) | (ty << 11) | dst;
}

// ---------------------------------------------------------------------------
// Fused centrality + LayerNorm1: h += emb; xn = LN(h)
// ---------------------------------------------------------------------------
__global__ __launch_bounds__(256)
void centrality_ln_kernel(const float* __restrict__ din_e,
                          const float* __restrict__ dout_e,
                          const float* __restrict__ gw,
                          const float* __restrict__ bw) {
    int n = blockIdx.x, tid = threadIdx.x;
    __shared__ float sh[9];
    int di = min(g_din[n],  MAXDEG);
    int dn = min(g_dout[n], MAXDEG);
    float x = g_h[n * DMODEL + tid]
            + din_e [(size_t)di * DMODEL + tid]
            + dout_e[(size_t)dn * DMODEL + tid];
    g_h[n * DMODEL + tid] = x;
    float v = x;
    #pragma unroll
    for (int o = 16; o >= 1; o >>= 1) v += __shfl_xor_sync(0xffffffffu, v, o);
    if ((tid & 31) == 0) sh[tid >> 5] = v;
    __syncthreads();
    if (tid == 0) {
        float s = 0.f;
        #pragma unroll
        for (int w = 0; w < 8; w++) s += sh[w];
        sh[8] = s * (1.0f / DMODEL);
    }
    __syncthreads();
    float mu = sh[8];
    float d = x - mu;
    v = d * d;
    #pragma unroll
    for (int o = 16; o >= 1; o >>= 1) v += __shfl_xor_sync(0xffffffffu, v, o);
    __syncthreads();
    if ((tid & 31) == 0) sh[tid >> 5] = v;
    __syncthreads();
    if (tid == 0) {
        float s = 0.f;
        #pragma unroll
        for (int w = 0; w < 8; w++) s += sh[w];
        sh[8] = s * (1.0f / DMODEL);
    }
    __syncthreads();
    float var = sh[8];
    g_xn[n * DMODEL + tid] = d * rsqrtf(var + 1e-5f) * gw[tid] + bw[tid];
}

// Plain LayerNorm (LN2)
__global__ __launch_bounds__(256)
void layernorm_kernel(const float* __restrict__ in, float* __restrict__ out,
                      const float* __restrict__ gw, const float* __restrict__ bw) {
    int row = blockIdx.x, tid = threadIdx.x;
    __shared__ float sh[9];
    float x = in[row * DMODEL + tid];
    float v = x;
    #pragma unroll
    for (int o = 16; o >= 1; o >>= 1) v += __shfl_xor_sync(0xffffffffu, v, o);
    if ((tid & 31) == 0) sh[tid >> 5] = v;
    __syncthreads();
    if (tid == 0) {
        float s = 0.f;
        #pragma unroll
        for (int w = 0; w < 8; w++) s += sh[w];
        sh[8] = s * (1.0f / DMODEL);
    }
    __syncthreads();
    float mu = sh[8];
    float d = x - mu;
    v = d * d;
    #pragma unroll
    for (int o = 16; o >= 1; o >>= 1) v += __shfl_xor_sync(0xffffffffu, v, o);
    __syncthreads();
    if ((tid & 31) == 0) sh[tid >> 5] = v;
    __syncthreads();
    if (tid == 0) {
        float s = 0.f;
        #pragma unroll
        for (int w = 0; w < 8; w++) s += sh[w];
        sh[8] = s * (1.0f / DMODEL);
    }
    __syncthreads();
    float var = sh[8];
    out[row * DMODEL + tid] = d * rsqrtf(var + 1e-5f) * gw[tid] + bw[tid];
}

// ---------------------------------------------------------------------------
// tf32 tensor-core GEMM: C = [R +] epi(A[M,K] @ B[K,N] + bias[N])
// BM=BN=64, BK=16, 256 threads = 8 warps (2x4 M x N).
// Warp tile 32x16 = 2x2 fragments of m16n8; mma.sync.m16n8k8.tf32.
// Operands converted to tf32 in the smem loader; double-buffered, 1 sync/slab.
// Smem strides: A [64][20] and B [16][72] -> conflict-free fragment LDS.
// ---------------------------------------------------------------------------
enum { EPI_NONE = 0, EPI_GELU = 1, EPI_RES = 2 };

template <int EPI>
__device__ __forceinline__
void sgemm_tc_body(const float* __restrict__ A, const float* __restrict__ B,
                   const float* __restrict__ bias, const float* R,
                   float* C, int M, int Nn, int K, int bx, int by) {
    __shared__ unsigned As[2][64][20];
    __shared__ unsigned Bs[2][16][72];

    const int tid  = threadIdx.x;
    const int lane = tid & 31;
    const int wid  = tid >> 5;
    const int g    = lane >> 2;      // groupID
    const int tg   = lane & 3;       // thread-in-group
    const int wm   = wid & 1;        // warp M index (0..1)
    const int wn   = wid >> 1;       // warp N index (0..3)
    const int am0  = wm * 32;
    const int bn0  = wn * 16;
    const int m0 = by * 64, n0 = bx * 64;

    // loader indices: one float4 of A and one float4 of B per thread per slab
    const int la_m = tid >> 2;            // 0..63
    const int la_k = (tid & 3) << 2;      // 0,4,8,12
    const int lb_k = tid >> 4;            // 0..15
    const int lb_n = (tid & 15) << 2;     // 0..60

    float acc[2][2][4];
    #pragma unroll
    for (int mi = 0; mi < 2; mi++)
        #pragma unroll
        for (int ni = 0; ni < 2; ni++)
            #pragma unroll
            for (int r = 0; r < 4; r++) acc[mi][ni][r] = 0.f;

    // prefetch slab 0
    float4 a4 = *(const float4*)(A + (size_t)(m0 + la_m) * K + la_k);
    float4 b4 = *(const float4*)(B + (size_t)lb_k * Nn + n0 + lb_n);
    {
        uint4 at = make_uint4(f2tf(a4.x), f2tf(a4.y), f2tf(a4.z), f2tf(a4.w));
        uint4 bt = make_uint4(f2tf(b4.x), f2tf(b4.y), f2tf(b4.z), f2tf(b4.w));
        *(uint4*)&As[0][la_m][la_k] = at;
        *(uint4*)&Bs[0][lb_k][lb_n] = bt;
    }
    __syncthreads();

    int cur = 0;
    for (int k0 = 0; k0 < K; k0 += 16) {
        const bool more = (k0 + 16 < K);
        if (more) {
            a4 = *(const float4*)(A + (size_t)(m0 + la_m) * K + k0 + 16 + la_k);
            b4 = *(const float4*)(B + (size_t)(k0 + 16 + lb_k) * Nn + n0 + lb_n);
        }
        const unsigned (*Asc)[20] = As[cur];
        const unsigned (*Bsc)[72] = Bs[cur];
        #pragma unroll
        for (int kk = 0; kk < 2; kk++) {
            const int kb = kk << 3;
            unsigned bf[2][2];
            #pragma unroll
            for (int ni = 0; ni < 2; ni++) {
                bf[ni][0] = Bsc[kb + tg    ][bn0 + ni * 8 + g];
                bf[ni][1] = Bsc[kb + tg + 4][bn0 + ni * 8 + g];
            }
            #pragma unroll
            for (int mi = 0; mi < 2; mi++) {
                const int r = am0 + mi * 16 + g;
                unsigned x0 = Asc[r    ][kb + tg];
                unsigned x1 = Asc[r + 8][kb + tg];
                unsigned x2 = Asc[r    ][kb + tg + 4];
                unsigned x3 = Asc[r + 8][kb + tg + 4];
                #pragma unroll
                for (int ni = 0; ni < 2; ni++)
                    mma_tf32(acc[mi][ni], x0, x1, x2, x3, bf[ni][0], bf[ni][1]);
            }
        }
        if (more) {
            int nxt = cur ^ 1;
            uint4 at = make_uint4(f2tf(a4.x), f2tf(a4.y), f2tf(a4.z), f2tf(a4.w));
            uint4 bt = make_uint4(f2tf(b4.x), f2tf(b4.y), f2tf(b4.z), f2tf(b4.w));
            *(uint4*)&As[nxt][la_m][la_k] = at;
            *(uint4*)&Bs[nxt][lb_k][lb_n] = bt;
        }
        __syncthreads();
        cur ^= 1;
    }

    // epilogue: bias + (gelu | residual), float2 stores
    #pragma unroll
    for (int mi = 0; mi < 2; mi++) {
        #pragma unroll
        for (int ni = 0; ni < 2; ni++) {
            int row = m0 + am0 + mi * 16 + g;
            int col = n0 + bn0 + ni * 8 + (tg << 1);
            float2 b2 = *(const float2*)(bias + col);
            float d0 = acc[mi][ni][0] + b2.x;
            float d1 = acc[mi][ni][1] + b2.y;
            float d2 = acc[mi][ni][2] + b2.x;
            float d3 = acc[mi][ni][3] + b2.y;
            if (EPI == EPI_GELU) {
                d0 = gelu_f(d0); d1 = gelu_f(d1);
                d2 = gelu_f(d2); d3 = gelu_f(d3);
            }
            size_t off0 = (size_t)row * Nn + col;
            size_t off1 = (size_t)(row + 8) * Nn + col;
            if (EPI == EPI_RES) {
                float2 r0 = *(const float2*)(R + off0);
                float2 r1 = *(const float2*)(R + off1);
                d0 += r0.x; d1 += r0.y; d2 += r1.x; d3 += r1.y;
            }
            *(float2*)(C + off0) = make_float2(d0, d1);
            *(float2*)(C + off1) = make_float2(d2, d3);
        }
    }
}

template <int EPI>
__global__ __launch_bounds__(256)
void sgemm_tc_kernel(const float* __restrict__ A, const float* __restrict__ B,
                     const float* __restrict__ bias, const float* R,
                     float* C, int M, int Nn, int K) {
    sgemm_tc_body<EPI>(A, B, bias, R, C, M, Nn, K, blockIdx.x, blockIdx.y);
}

// Fused Q/K/V projection: grid (12, 32); blockIdx.x>>2 selects matrix.
__global__ __launch_bounds__(256)
void qkv_kernel(const float* __restrict__ xn,
                const float* __restrict__ Wq, const float* __restrict__ Wk,
                const float* __restrict__ Wv,
                const float* __restrict__ bq, const float* __restrict__ bk,
                const float* __restrict__ bv) {
    int which = blockIdx.x >> 2;
    int bx = blockIdx.x & 3;
    const float* B  = (which == 0) ? Wq : (which == 1) ? Wk : Wv;
    const float* bb = (which == 0) ? bq : (which == 1) ? bk : bv;
    float* C        = (which == 0) ? g_q : (which == 1) ? g_k : g_v;
    sgemm_tc_body<EPI_NONE>(xn, B, bb, nullptr, C, NNODE, DMODEL, DMODEL,
                            bx, blockIdx.y);
}

// ---------------------------------------------------------------------------
// Flash attention v4: no-max single-pass softmax, scatter-first edge bias,
// per-block counting sort of the edge list by dst tile, packed SPD buckets.
// Block = (head, 64-row tile), 256 threads, dynamic smem. 4 syncs / tile.
// ---------------------------------------------------------------------------
#define PSTR 68

// dynamic smem layout (float offsets)
#define SM_QS   0                        // [32][68] = 2176
#define SM_KS   2176                     // [32][68]
#define SM_VS   4352                     // [64][36] = 2304
#define SM_PS   6656                     // [64][68] = 4352
#define SM_SE   11008                    // unsigned [ECAP]
#define SM_LS   (SM_SE + ECAP)           // [64]
#define SM_STH  (SM_LS + 64)             // [11] (pad 12)
#define SM_ETAB (SM_STH + 12)            // [8]
#define SM_BCNT (SM_ETAB + 8)            // int [32]
#define SM_BOFF (SM_BCNT + 32)           // int [33]
#define SM_BCUR (SM_BOFF + 33)           // int [32]
#define SM_TOTF (SM_BCUR + 32)
#define ATTN_SMEM_BYTES (SM_TOTF * 4)

__global__ __launch_bounds__(256)
void flash_attn4_kernel(const float* __restrict__ spd_t,   // layer slice [11][8]
                        const float* __restrict__ edge_t)  // layer slice [8][8]
{
    extern __shared__ float sm[];
    float (*Qs)[68] = (float (*)[68])(sm + SM_QS);
    float (*Ks)[68] = (float (*)[68])(sm + SM_KS);
    float (*Vs)[36] = (float (*)[36])(sm + SM_VS);
    float* Ps    = sm + SM_PS;
    unsigned* Se = (unsigned*)(sm + SM_SE);
    float* lS    = sm + SM_LS;
    float* sth   = sm + SM_STH;
    float* etab  = sm + SM_ETAB;
    int* bcnt    = (int*)(sm + SM_BCNT);
    int* boff    = (int*)(sm + SM_BOFF);
    int* bcur    = (int*)(sm + SM_BCUR);

    const int h   = blockIdx.y;
    const int r0  = blockIdx.x * 64;
    const int tid = threadIdx.x;
    const int ty = tid >> 4, tx = tid & 15;     // QK mapping
    const int half = tid >> 7;                  // PV mapping
    const int t7 = tid & 127;
    const int pr = t7 >> 3, pc = t7 & 7;
    const float scale = 0.17677669529663687f;   // 1/sqrt(32)

    // per-head tables + bucket counters
    if (tid < 11)      sth[tid] = spd_t[tid * 8 + h];
    else if (tid < 19) etab[tid - 11] = edge_t[(tid - 11) * 8 + h];
    if (tid < 32) bcnt[tid] = 0;
    __syncthreads();

    // counting sort of this row-block's edges by dst tile
    const int eoff = g_rowptr[r0];
    const int cnt  = min(g_rowptr[r0 + 64] - eoff, ECAP);
    for (int i = tid; i < cnt; i += 256)
        atomicAdd(&bcnt[(g_ecsr[eoff + i] & 0x7FFu) >> 6], 1);
    __syncthreads();
    if (tid == 0) {
        int run = 0;
        #pragma unroll
        for (int b = 0; b < 32; b++) { boff[b] = run; run += bcnt[b]; }
        boff[32] = run;
    }
    __syncthreads();
    if (tid < 32) bcur[tid] = boff[tid];
    __syncthreads();
    for (int i = tid; i < cnt; i += 256) {
        unsigned e = g_ecsr[eoff + i];
        int b = (e & 0x7FFu) >> 6;
        Se[atomicAdd(&bcur[b], 1)] = e;
    }

    // Q tile, transposed + pre-scaled
    {
        int qr = tid >> 2;
        int qd = (tid & 3) << 3;
        const float* qp = g_q + (size_t)(r0 + qr) * DMODEL + h * DHEAD + qd;
        float4 q0 = *(const float4*)qp;
        float4 q1 = *(const float4*)(qp + 4);
        Qs[qd + 0][qr] = q0.x * scale; Qs[qd + 1][qr] = q0.y * scale;
        Qs[qd + 2][qr] = q0.z * scale; Qs[qd + 3][qr] = q0.w * scale;
        Qs[qd + 4][qr] = q1.x * scale; Qs[qd + 5][qr] = q1.y * scale;
        Qs[qd + 6][qr] = q1.z * scale; Qs[qd + 7][qr] = q1.w * scale;
    }

    float l[4], acc[4][4];
    #pragma unroll
    for (int i = 0; i < 4; i++) {
        l[i] = 0.f;
        #pragma unroll
        for (int j = 0; j < 4; j++) acc[i][j] = 0.f;
    }

    for (int tile = 0; tile < NNODE / 64; tile++) {
        const int c0 = tile * 64;
        __syncthreads();   // Ps/Ks/Vs free (first iter: Se/boff/Qs ready)

        // zero Ps (scatter target) + load K/V tiles
        {
            float4 z4 = make_float4(0.f, 0.f, 0.f, 0.f);
            for (int v = tid; v < (64 * PSTR) / 4; v += 256)
                ((float4*)Ps)[v] = z4;
        }
        {
            int kr = tid >> 2;
            int kd = (tid & 3) << 3;
            const float* kp = g_k + (size_t)(c0 + kr) * DMODEL + h * DHEAD + kd;
            const float* vp = g_v + (size_t)(c0 + kr) * DMODEL + h * DHEAD + kd;
            float4 k0v = *(const float4*)kp;
            float4 k1v = *(const float4*)(kp + 4);
            float4 v0v = *(const float4*)vp;
            float4 v1v = *(const float4*)(vp + 4);
            Ks[kd + 0][kr] = k0v.x; Ks[kd + 1][kr] = k0v.y;
            Ks[kd + 2][kr] = k0v.z; Ks[kd + 3][kr] = k0v.w;
            Ks[kd + 4][kr] = k1v.x; Ks[kd + 5][kr] = k1v.y;
            Ks[kd + 6][kr] = k1v.z; Ks[kd + 7][kr] = k1v.w;
            *(float4*)&Vs[kr][kd]     = v0v;
            *(float4*)&Vs[kr][kd + 4] = v1v;
        }
        __syncthreads();   // Ps zeroed, K/V ready

        // edge bias scatter (only this tile's bucket)
        {
            int s0 = boff[tile], s1 = boff[tile + 1];
            for (int i = s0 + tid; i < s1; i += 256) {
                unsigned e = Se[i];
                atomicAdd(&Ps[((e >> 14) - (unsigned)r0) * PSTR + (e & 63u)],
                          etab[(e >> 11) & 7u]);
            }
        }
        __syncthreads();   // edge bias in Ps

        // QK^T with SPD (packed buckets) + edge bias; single-pass exp
        float s[4][4];
        #pragma unroll
        for (int i = 0; i < 4; i++) {
            int rloc = (ty << 2) + i;
            float4 eb = *(const float4*)&Ps[rloc * PSTR + (tx << 2)];
            unsigned bk4 = g_sbu[((size_t)(r0 + rloc) * NNODE + c0 + (tx << 2)) >> 2];
            s[i][0] = eb.x + sth[bk4 & 255u];
            s[i][1] = eb.y + sth[(bk4 >> 8) & 255u];
            s[i][2] = eb.z + sth[(bk4 >> 16) & 255u];
            s[i][3] = eb.w + sth[bk4 >> 24];
        }
        #pragma unroll
        for (int k = 0; k < 32; k++) {
            float4 av = *(const float4*)&Qs[k][ty << 2];
            float4 bv = *(const float4*)&Ks[k][tx << 2];
            float ar[4] = {av.x, av.y, av.z, av.w};
            float br[4] = {bv.x, bv.y, bv.z, bv.w};
            #pragma unroll
            for (int i = 0; i < 4; i++)
                #pragma unroll
                for (int j = 0; j < 4; j++)
                    s[i][j] += ar[i] * br[j];
        }
        #pragma unroll
        for (int i = 0; i < 4; i++) {
            int rloc = (ty << 2) + i;
            float p0 = __expf(s[i][0]);
            float p1 = __expf(s[i][1]);
            float p2 = __expf(s[i][2]);
            float p3 = __expf(s[i][3]);
            l[i] += p0 + p1 + p2 + p3;
            *(float4*)&Ps[rloc * PSTR + (tx << 2)] = make_float4(p0, p1, p2, p3);
        }
        __syncthreads();   // P ready

        // P @ V (split-k over halves; vectorized P and V loads, no corr)
        {
            const int jbase = half << 5;
            #pragma unroll
            for (int ch = 0; ch < 8; ch++) {
                const int j0 = jbase + (ch << 2);
                float p[4][4];
                #pragma unroll
                for (int i = 0; i < 4; i++) {
                    float4 p4 = *(const float4*)&Ps[((pr << 2) + i) * PSTR + j0];
                    p[i][0] = p4.x; p[i][1] = p4.y; p[i][2] = p4.z; p[i][3] = p4.w;
                }
                #pragma unroll
                for (int jv = 0; jv < 4; jv++) {
                    float4 v4 = *(const float4*)&Vs[j0 + jv][pc << 2];
                    #pragma unroll
                    for (int i = 0; i < 4; i++) {
                        acc[i][0] += p[i][jv] * v4.x;
                        acc[i][1] += p[i][jv] * v4.y;
                        acc[i][2] += p[i][jv] * v4.z;
                        acc[i][3] += p[i][jv] * v4.w;
                    }
                }
            }
        }
    }

    // Reduce l across the 16 tx lanes (once), publish
    #pragma unroll
    for (int i = 0; i < 4; i++) {
        float v = l[i];
        v += __shfl_xor_sync(0xffffffffu, v, 1);
        v += __shfl_xor_sync(0xffffffffu, v, 2);
        v += __shfl_xor_sync(0xffffffffu, v, 4);
        v += __shfl_xor_sync(0xffffffffu, v, 8);
        l[i] = v;
    }
    __syncthreads();
    if (tx == 0) {
        #pragma unroll
        for (int i = 0; i < 4; i++) lS[(ty << 2) + i] = l[i];
    }
    __syncthreads();

    // Reduce halves via smem, normalize, write out
    float* obuf = Ps;   // reuse as [64][36]
    if (half == 1) {
        #pragma unroll
        for (int i = 0; i < 4; i++)
            *(float4*)&obuf[((pr << 2) + i) * 36 + (pc << 2)] =
                make_float4(acc[i][0], acc[i][1], acc[i][2], acc[i][3]);
    }
    __syncthreads();
    if (half == 0) {
        #pragma unroll
        for (int i = 0; i < 4; i++) {
            int rloc = (pr << 2) + i;
            float4 o = *(const float4*)&obuf[rloc * 36 + (pc << 2)];
            float inv = 1.0f / lS[rloc];
            *(float4*)(g_attn + (size_t)(r0 + rloc) * DMODEL + h * DHEAD + (pc << 2)) =
                make_float4((acc[i][0] + o.x) * inv, (acc[i][1] + o.y) * inv,
                            (acc[i][2] + o.z) * inv, (acc[i][3] + o.w) * inv);
        }
    }
}

// ---------------------------------------------------------------------------
// Host launch
// ---------------------------------------------------------------------------
extern "C" void kernel_launch(void* const* d_in, const int* in_sizes, int n_in,
                              void* d_out, int out_size) {
    const float* x     = (const float*)d_in[0];
    const int*   ei    = (const int*)  d_in[1];
    const int*   et    = (const int*)  d_in[2];
    const float* pos   = (const float*)d_in[3];
    const float* W_emb = (const float*)d_in[4];
    const float* b_emb = (const float*)d_in[5];
    const float* Wq    = (const float*)d_in[6];
    const float* Wk    = (const float*)d_in[7];
    const float* Wv    = (const float*)d_in[8];
    const float* Wo    = (const float*)d_in[9];
    const float* bq    = (const float*)d_in[10];
    const float* bk    = (const float*)d_in[11];
    const float* bv    = (const float*)d_in[12];
    const float* bo    = (const float*)d_in[13];
    const float* spd_t = (const float*)d_in[14];
    const float* edge_t= (const float*)d_in[15];
    const float* din_e = (const float*)d_in[16];
    const float* dout_e= (const float*)d_in[17];
    const float* ln1g  = (const float*)d_in[18];
    const float* ln1b  = (const float*)d_in[19];
    const float* ln2g  = (const float*)d_in[20];
    const float* ln2b  = (const float*)d_in[21];
    const float* W1    = (const float*)d_in[22];
    const float* b1    = (const float*)d_in[23];
    const float* W2    = (const float*)d_in[24];
    const float* b2    = (const float*)d_in[25];
    const float* Wout  = (const float*)d_in[26];
    const float* bout  = (const float*)d_in[27];
    float* out = (float*)d_out;

    float *p_h, *p_xn, *p_attn, *p_ffn;
    cudaGetSymbolAddress((void**)&p_h,    g_h);
    cudaGetSymbolAddress((void**)&p_xn,   g_xn);
    cudaGetSymbolAddress((void**)&p_attn, g_attn);
    cudaGetSymbolAddress((void**)&p_ffn,  g_ffn);

    // idempotent; called every launch (no static guards allowed)
    cudaFuncSetAttribute(flash_attn4_kernel,
                         cudaFuncAttributeMaxDynamicSharedMemorySize,
                         ATTN_SMEM_BYTES);

    // Graph-structural precompute
    spdb_kernel<<<(NN_TOT / 4 + 255) / 256, 256>>>(pos);
    deg_zero_kernel<<<(NNODE + 255) / 256, 256>>>();
    deg_acc_kernel<<<(NEDGE + 255) / 256, 256>>>(ei);
    csr_scan_kernel<<<1, 256>>>();
    csr_scatter_kernel<<<(NEDGE + 255) / 256, 256>>>(ei, et);

    // Node embedding: h = x @ W_emb + b_emb
    sgemm_tc_kernel<EPI_NONE><<<dim3(DMODEL / 64, NNODE / 64), 256>>>(
        x, W_emb, b_emb, nullptr, p_h, NNODE, DMODEL, DFEAT);

    for (int l = 0; l < 2; l++) {
        centrality_ln_kernel<<<NNODE, 256>>>(
            din_e + (size_t)l * 513 * DMODEL, dout_e + (size_t)l * 513 * DMODEL,
            ln1g + l * DMODEL, ln1b + l * DMODEL);
        qkv_kernel<<<dim3(12, NNODE / 64), 256>>>(
            p_xn,
            Wq + (size_t)l * DMODEL * DMODEL,
            Wk + (size_t)l * DMODEL * DMODEL,
            Wv + (size_t)l * DMODEL * DMODEL,
            bq + l * DMODEL, bk + l * DMODEL, bv + l * DMODEL);
        flash_attn4_kernel<<<dim3(NNODE / 64, NHEAD), 256, ATTN_SMEM_BYTES>>>(
            spd_t + l * 88, edge_t + l * 64);
        sgemm_tc_kernel<EPI_RES><<<dim3(DMODEL / 64, NNODE / 64), 256>>>(
            p_attn, Wo + (size_t)l * DMODEL * DMODEL, bo + l * DMODEL, p_h, p_h,
            NNODE, DMODEL, DMODEL);
        layernorm_kernel<<<NNODE, 256>>>(p_h, p_xn, ln2g + l * DMODEL, ln2b + l * DMODEL);
        sgemm_tc_kernel<EPI_GELU><<<dim3(DFF / 64, NNODE / 64), 256>>>(
            p_xn, W1 + (size_t)l * DMODEL * DFF, b1 + l * DFF, nullptr, p_ffn,
            NNODE, DFF, DMODEL);
        sgemm_tc_kernel<EPI_RES><<<dim3(DMODEL / 64, NNODE / 64), 256>>>(
            p_ffn, W2 + (size_t)l * DFF * DMODEL, b2 + l * DMODEL, p_h, p_h,
            NNODE, DMODEL, DFF);
    }

    // output head
    sgemm_tc_kernel<EPI_NONE><<<dim3(DOUTF / 64, NNODE / 64), 256>>>(
        p_h, Wout, bout, nullptr, out, NNODE, DOUTF, DMODEL);
}